// round 5
// baseline (speedup 1.0000x reference)
#include <cuda_runtime.h>

#define BSZ 256
#define HSZ 512
#define NSZ 16
#define TSTEPS 63
#define ODIM 9
#define KC 16           // split-K chunks
#define KCH 32          // K per chunk

typedef unsigned long long ull;

// ---------- packed f32x2 helpers (sm_103a FFMA2 path, PTX-only) ----------
__device__ __forceinline__ ull pack2(float lo, float hi) {
    ull r; asm("mov.b64 %0,{%1,%2};" : "=l"(r) : "f"(lo), "f"(hi)); return r;
}
__device__ __forceinline__ float2 unpack2(ull v) {
    float2 r; asm("mov.b64 {%0,%1},%2;" : "=f"(r.x), "=f"(r.y) : "l"(v)); return r;
}
__device__ __forceinline__ ull fma2v(ull a, ull b, ull c) {
    ull d; asm("fma.rn.f32x2 %0,%1,%2,%3;" : "=l"(d) : "l"(a), "l"(b), "l"(c)); return d;
}

__device__ __forceinline__ float gelu_exact(float x) {
    return 0.5f * x * (1.0f + erff(x * 0.70710678118654752440f));
}
__device__ __forceinline__ float sigm(float x) {
    return 1.0f / (1.0f + expf(-x));
}

// ---------- scratch (__device__ globals; no allocation allowed) ----------
__device__ __align__(16) float g_enc[BSZ * 6 * HSZ];          // encoded[:, 0:6, :] only
__device__ __align__(16) float g_states[2 * BSZ * HSZ * NSZ]; // SSM states per layer
__device__ __align__(16) float g_gact[BSZ * HSZ];             // gelu(y) GEMM input
__device__ __align__(16) float g_dp[BSZ * HSZ];               // decoder proj (step 0)
__device__ __align__(16) float g_ctx[BSZ * HSZ];
__device__ __align__(16) float g_part[KC * BSZ * HSZ];        // split-K GEMM partials

// ============================================================
// encoded = input_seq @ in_W + in_b  (only s < 6 ever read: ptr in [0,6))
// ============================================================
__global__ void k_enc(const float* __restrict__ inseq,
                      const float* __restrict__ inW,
                      const float* __restrict__ inb) {
    int idx = blockIdx.x * 256 + threadIdx.x;   // < B*6*H
    int h = idx & (HSZ - 1);
    int bs = idx >> 9;                          // b*6 + s
    int b = bs / 6, s = bs - b * 6;
    const float* r = inseq + (b * 64 + s) * 3;
    g_enc[idx] = fmaf(r[0], inW[h],
                 fmaf(r[1], inW[HSZ + h],
                 fmaf(r[2], inW[2 * HSZ + h], inb[h])));
}

// ============================================================
// zero layer-1 states / ctx (layer-0 states fully written by k_first)
// ============================================================
__global__ void k_init() {
    int idx = blockIdx.x * 256 + threadIdx.x;
    if (idx < 2 * BSZ * HSZ * NSZ) g_states[idx] = 0.0f;
    if (idx < BSZ * HSZ) g_ctx[idx] = 0.0f;
}

// ============================================================
// Step-0 decoder proj + layer-0 SSM (dec0 = [0,0,1], states = 0)
// ============================================================
__global__ void __launch_bounds__(256)
k_first(const float* __restrict__ inW, const float* __restrict__ inb,
        const float* __restrict__ A0, const float* __restrict__ B0,
        const float* __restrict__ C0, const float* __restrict__ D0) {
    int idx = blockIdx.x * 256 + threadIdx.x;   // < B*H
    int h = idx & (HSZ - 1);
    int b = idx >> 9;
    float x = inW[2 * HSZ + h] + inb[h];
    g_dp[idx] = x;

    const float4* B4 = (const float4*)(B0 + h * NSZ);
    const float4* C4 = (const float4*)(C0 + h * NSZ);
    float4* S4p = (float4*)(g_states + ((size_t)b * HSZ + h) * NSZ);
    float acc = 0.0f;
#pragma unroll
    for (int q = 0; q < 4; q++) {
        float4 bm = B4[q], c = C4[q];
        float4 s = make_float4(bm.x * x, bm.y * x, bm.z * x, bm.w * x);
        acc += c.x * s.x + c.y * s.y + c.z * s.z + c.w * s.w;
        S4p[q] = s;
    }
    g_gact[idx] = gelu_exact(fmaf(D0[h], x, acc));
}

// ============================================================
// Split-K GEMM: g_part[z] = g_gact(256x512) @ W k-chunk z
// grid (4 ncb, 4 mrb, 16 kc), 256 threads. Block tile 64x128, chunk 32.
// Thread tile 4 rows x 8 cols, column-pair f32x2 (A pre-duplicated in smem,
// B packed col-pairs straight from LDS.128 -> no pack MOVs in the loop).
// ============================================================
__global__ void __launch_bounds__(256)
k_gemm(const float* __restrict__ W) {
    __shared__ ull Asd[KCH][65];      // duplicated (a,a), transposed [k][row]
    __shared__ float Bs[KCH][128];
    int t = threadIdx.x;
    int n0 = blockIdx.x * 128, m0 = blockIdx.y * 64, k0 = blockIdx.z * KCH;

    // stage A: 64 rows x 32 k, transposed + duplicated (2 float4 loads/thread)
    {
        int kk = (t & 7) * 4, rr = t >> 3;          // rr 0..31
#pragma unroll
        for (int p = 0; p < 2; p++) {
            int r = rr + 32 * p;
            float4 v = *(const float4*)&g_gact[(m0 + r) * HSZ + k0 + kk];
            Asd[kk + 0][r] = pack2(v.x, v.x);
            Asd[kk + 1][r] = pack2(v.y, v.y);
            Asd[kk + 2][r] = pack2(v.z, v.z);
            Asd[kk + 3][r] = pack2(v.w, v.w);
        }
    }
    // stage B: 32 k x 128 cols (4 float4 loads/thread)
    {
        int cc = (t & 31) * 4, kk = t >> 5;         // kk 0..7
#pragma unroll
        for (int p = 0; p < 4; p++)
            *(float4*)&Bs[kk + 8 * p][cc] = *(const float4*)&W[(k0 + kk + 8 * p) * HSZ + n0 + cc];
    }
    __syncthreads();

    int tx = t & 15;          // col group: cols n0 + tx*8 .. +8
    int ty = t >> 4;          // row group: rows m0 + ty*4 .. +4

    ull acc[4][4];
#pragma unroll
    for (int i = 0; i < 4; i++)
#pragma unroll
        for (int j = 0; j < 4; j++) acc[i][j] = 0ULL;

#pragma unroll 8
    for (int k = 0; k < KCH; k++) {
        ulonglong2 b01 = *(const ulonglong2*)&Bs[k][tx * 8];       // cols (0,1),(2,3)
        ulonglong2 b23 = *(const ulonglong2*)&Bs[k][tx * 8 + 4];   // cols (4,5),(6,7)
#pragma unroll
        for (int p = 0; p < 4; p++) {
            ull a = Asd[k][ty * 4 + p];                            // (a,a) broadcast
            acc[p][0] = fma2v(a, b01.x, acc[p][0]);
            acc[p][1] = fma2v(a, b01.y, acc[p][1]);
            acc[p][2] = fma2v(a, b23.x, acc[p][2]);
            acc[p][3] = fma2v(a, b23.y, acc[p][3]);
        }
    }

    float* P = g_part + (size_t)blockIdx.z * BSZ * HSZ;
#pragma unroll
    for (int p = 0; p < 4; p++) {
        int row = m0 + ty * 4 + p;
        float2 v0 = unpack2(acc[p][0]), v1 = unpack2(acc[p][1]);
        float2 v2 = unpack2(acc[p][2]), v3 = unpack2(acc[p][3]);
        int c = n0 + tx * 8;
        *(float4*)&P[row * HSZ + c]     = make_float4(v0.x, v0.y, v1.x, v1.y);
        *(float4*)&P[row * HSZ + c + 4] = make_float4(v2.x, v2.y, v3.x, v3.y);
    }
}

// ============================================================
// ssm1: z0 = sum(partials)+bias (+residual), LN -> x, layer-1 SSM -> g_gact
// 2 batch rows per block (coeffs loaded once), 128 blocks x 512 thr (t = h)
// ============================================================
__global__ void __launch_bounds__(512)
k_ssm1(int isstep0,
       const float* __restrict__ ob0, const float* __restrict__ lng0,
       const float* __restrict__ lnb0,
       const float* __restrict__ A1, const float* __restrict__ B1,
       const float* __restrict__ C1, const float* __restrict__ D1) {
    __shared__ float red[68];
    int b0 = blockIdx.x * 2, t = threadIdx.x;
    int lane = t & 31, w = t >> 5;

    float y0 = 0.0f, y1 = 0.0f;
    const float* P = g_part + (size_t)b0 * HSZ + t;
#pragma unroll
    for (int z = 0; z < KC; z++) {
        y0 += P[(size_t)z * BSZ * HSZ];
        y1 += P[(size_t)z * BSZ * HSZ + HSZ];
    }
    float bias = ob0[t];
    y0 += bias; y1 += bias;
    float z0, z1;
    if (isstep0) {
        z0 = y0 + g_dp[b0 * HSZ + t];
        z1 = y1 + g_dp[(b0 + 1) * HSZ + t];
    } else { z0 = 2.0f * y0; z1 = 2.0f * y1; }

    float s0 = z0, q0 = z0 * z0, s1 = z1, q1 = z1 * z1;
#pragma unroll
    for (int d = 16; d; d >>= 1) {
        s0 += __shfl_xor_sync(0xFFFFFFFFu, s0, d);
        q0 += __shfl_xor_sync(0xFFFFFFFFu, q0, d);
        s1 += __shfl_xor_sync(0xFFFFFFFFu, s1, d);
        q1 += __shfl_xor_sync(0xFFFFFFFFu, q1, d);
    }
    if (lane == 0) { red[w] = s0; red[16 + w] = q0; red[32 + w] = s1; red[48 + w] = q1; }
    __syncthreads();
    if (t == 0) {
        float a0 = 0, b0s = 0, a1 = 0, b1s = 0;
#pragma unroll
        for (int i = 0; i < 16; i++) { a0 += red[i]; b0s += red[16 + i]; a1 += red[32 + i]; b1s += red[48 + i]; }
        float m0 = a0 * (1.0f / HSZ), m1 = a1 * (1.0f / HSZ);
        red[64] = m0; red[65] = rsqrtf(b0s * (1.0f / HSZ) - m0 * m0 + 1e-5f);
        red[66] = m1; red[67] = rsqrtf(b1s * (1.0f / HSZ) - m1 * m1 + 1e-5f);
    }
    __syncthreads();
    float g = lng0[t], bb = lnb0[t];
    float x0 = (z0 - red[64]) * red[65] * g + bb;
    float x1 = (z1 - red[66]) * red[67] * g + bb;

    const float4* A4 = (const float4*)(A1 + t * NSZ);
    const float4* B4 = (const float4*)(B1 + t * NSZ);
    const float4* C4 = (const float4*)(C1 + t * NSZ);
    float4* S0 = (float4*)(g_states + ((size_t)BSZ * HSZ + (size_t)b0 * HSZ + t) * NSZ);
    float4* S1 = S0 + (HSZ * NSZ / 4);
    float acc0 = 0.0f, acc1 = 0.0f;
#pragma unroll
    for (int q = 0; q < 4; q++) {
        float4 a = A4[q], bm = B4[q], c = C4[q];
        float4 s = S0[q];
        s.x = fmaf(a.x, s.x, bm.x * x0); s.y = fmaf(a.y, s.y, bm.y * x0);
        s.z = fmaf(a.z, s.z, bm.z * x0); s.w = fmaf(a.w, s.w, bm.w * x0);
        acc0 += c.x * s.x + c.y * s.y + c.z * s.z + c.w * s.w;
        S0[q] = s;
        s = S1[q];
        s.x = fmaf(a.x, s.x, bm.x * x1); s.y = fmaf(a.y, s.y, bm.y * x1);
        s.z = fmaf(a.z, s.z, bm.z * x1); s.w = fmaf(a.w, s.w, bm.w * x1);
        acc1 += c.x * s.x + c.y * s.y + c.z * s.z + c.w * s.w;
        S1[q] = s;
    }
    float dd = D1[t];
    g_gact[b0 * HSZ + t] = gelu_exact(fmaf(dd, x0, acc0));
    g_gact[(b0 + 1) * HSZ + t] = gelu_exact(fmaf(dd, x1, acc1));
}

// ============================================================
// head (+ fused next-step decoder proj & layer-0 SSM)
// 2 batch rows per block, 128 blocks x 512 thr
// ============================================================
__global__ void __launch_bounds__(512)
k_head(int step,
       const float* __restrict__ ob1, const float* __restrict__ lng1,
       const float* __restrict__ lnb1,
       const float* __restrict__ hW, const float* __restrict__ hb,
       const float* __restrict__ inW, const float* __restrict__ inb,
       const float* __restrict__ A0, const float* __restrict__ B0,
       const float* __restrict__ C0, const float* __restrict__ D0,
       float* __restrict__ out) {
    __shared__ float xdc[2][HSZ];
    __shared__ float red[68];
    __shared__ float gv[2][12];
    __shared__ float decs[2][3];
    __shared__ int ptr_s[2];

    int b0 = blockIdx.x * 2, t = threadIdx.x;
    int lane = t & 31, w = t >> 5;

    float y0 = 0.0f, y1 = 0.0f;
    const float* P = g_part + (size_t)b0 * HSZ + t;
#pragma unroll
    for (int z = 0; z < KC; z++) {
        y0 += P[(size_t)z * BSZ * HSZ];
        y1 += P[(size_t)z * BSZ * HSZ + HSZ];
    }
    float bias = ob1[t];
    y0 += bias; y1 += bias;
    float z0, z1;
    if (step == 0) {
        z0 = y0 + g_dp[b0 * HSZ + t];
        z1 = y1 + g_dp[(b0 + 1) * HSZ + t];
    } else { z0 = 2.0f * y0; z1 = 2.0f * y1; }

    float s0 = z0, q0 = z0 * z0, s1 = z1, q1 = z1 * z1;
#pragma unroll
    for (int d = 16; d; d >>= 1) {
        s0 += __shfl_xor_sync(0xFFFFFFFFu, s0, d);
        q0 += __shfl_xor_sync(0xFFFFFFFFu, q0, d);
        s1 += __shfl_xor_sync(0xFFFFFFFFu, s1, d);
        q1 += __shfl_xor_sync(0xFFFFFFFFu, q1, d);
    }
    if (lane == 0) { red[w] = s0; red[16 + w] = q0; red[32 + w] = s1; red[48 + w] = q1; }
    __syncthreads();
    if (t == 0) {
        float a0 = 0, c0 = 0, a1 = 0, c1 = 0;
#pragma unroll
        for (int i = 0; i < 16; i++) { a0 += red[i]; c0 += red[16 + i]; a1 += red[32 + i]; c1 += red[48 + i]; }
        float m0 = a0 * (1.0f / HSZ), m1 = a1 * (1.0f / HSZ);
        red[64] = m0; red[65] = rsqrtf(c0 * (1.0f / HSZ) - m0 * m0 + 1e-5f);
        red[66] = m1; red[67] = rsqrtf(c1 * (1.0f / HSZ) - m1 * m1 + 1e-5f);
    }
    __syncthreads();
    float g = lng1[t], bbl = lnb1[t];
    float xd0 = (z0 - red[64]) * red[65] * g + bbl;
    float xd1 = (z1 - red[66]) * red[67] * g + bbl;
    float ctx0 = g_ctx[b0 * HSZ + t];
    float ctx1 = g_ctx[(b0 + 1) * HSZ + t];
    xdc[0][t] = xd0 + ctx0;
    xdc[1][t] = xd1 + ctx1;
    __syncthreads();

    // head logits for both rows: warp w (<9) computes the two dots
    if (w < ODIM) {
        float a0 = 0.0f, a1 = 0.0f;
#pragma unroll
        for (int q = 0; q < 16; q++) {
            int k = q * 32 + lane;
            float wk = hW[k * ODIM + w];
            a0 = fmaf(xdc[0][k], wk, a0);
            a1 = fmaf(xdc[1][k], wk, a1);
        }
#pragma unroll
        for (int d = 16; d; d >>= 1) {
            a0 += __shfl_xor_sync(0xFFFFFFFFu, a0, d);
            a1 += __shfl_xor_sync(0xFFFFFFFFu, a1, d);
        }
        if (lane == 0) { gv[0][w] = a0 + hb[w]; gv[1][w] = a1 + hb[w]; }
    }
    __syncthreads();

    bool is_out = ((step & 1) == 0);
    if (is_out) {
        if (t < ODIM) out[b0 * (TSTEPS * ODIM) + step * ODIM + t] = sigm(gv[0][t]);
        if (t >= 32 && t < 32 + ODIM)
            out[(b0 + 1) * (TSTEPS * ODIM) + step * ODIM + (t - 32)] = sigm(gv[1][t - 32]);
        if (t < 2) {
            decs[t][0] = (sigm(gv[t][0]) > 0.5f) ? 1.0f : 0.0f;
            decs[t][1] = 1.0f; decs[t][2] = 0.0f;
        }
    } else {
        if (t < 2) {
            float best = sigm(gv[t][3]); int p = 0;
#pragma unroll
            for (int c = 1; c < 6; c++) {
                float v = sigm(gv[t][3 + c]);
                if (v > best) { best = v; p = c; }
            }
            ptr_s[t] = p;
            decs[t][0] = 0.0f; decs[t][1] = 0.0f; decs[t][2] = 1.0f;
        }
        __syncthreads();                       // uniform branch: safe
        const float* ev0 = g_enc + (b0 * 6 + ptr_s[0]) * HSZ;
        const float* ev1 = g_enc + ((b0 + 1) * 6 + ptr_s[1]) * HSZ;
        g_ctx[b0 * HSZ + t] = ctx0 + ev0[t];
        g_ctx[(b0 + 1) * HSZ + t] = ctx1 + ev1[t];
        if (w < ODIM) {
            float a0 = 0.0f, a1 = 0.0f;
#pragma unroll
            for (int q = 0; q < 16; q++) {
                int k = q * 32 + lane;
                float wk = hW[k * ODIM + w];
                a0 = fmaf(ev0[k], wk, a0);
                a1 = fmaf(ev1[k], wk, a1);
            }
#pragma unroll
            for (int d = 16; d; d >>= 1) {
                a0 += __shfl_xor_sync(0xFFFFFFFFu, a0, d);
                a1 += __shfl_xor_sync(0xFFFFFFFFu, a1, d);
            }
            if (lane == 0) {
                out[b0 * (TSTEPS * ODIM) + step * ODIM + w] = sigm(gv[0][w] + a0);
                out[(b0 + 1) * (TSTEPS * ODIM) + step * ODIM + w] = sigm(gv[1][w] + a1);
            }
        }
    }
    __syncthreads();

    // fused next-step: decoder proj + layer-0 SSM for both rows (coeffs once)
    float w0 = inW[t], w1 = inW[HSZ + t], w2 = inW[2 * HSZ + t], ib = inb[t];
    float x0 = fmaf(decs[0][0], w0, fmaf(decs[0][1], w1, fmaf(decs[0][2], w2, ib)));
    float x1 = fmaf(decs[1][0], w0, fmaf(decs[1][1], w1, fmaf(decs[1][2], w2, ib)));

    const float4* A4 = (const float4*)(A0 + t * NSZ);
    const float4* B4 = (const float4*)(B0 + t * NSZ);
    const float4* C4 = (const float4*)(C0 + t * NSZ);
    float4* S0 = (float4*)(g_states + ((size_t)b0 * HSZ + t) * NSZ);
    float4* S1 = S0 + (HSZ * NSZ / 4);
    float acc0 = 0.0f, acc1 = 0.0f;
#pragma unroll
    for (int q = 0; q < 4; q++) {
        float4 a = A4[q], bm = B4[q], c = C4[q];
        float4 s = S0[q];
        s.x = fmaf(a.x, s.x, bm.x * x0); s.y = fmaf(a.y, s.y, bm.y * x0);
        s.z = fmaf(a.z, s.z, bm.z * x0); s.w = fmaf(a.w, s.w, bm.w * x0);
        acc0 += c.x * s.x + c.y * s.y + c.z * s.z + c.w * s.w;
        S0[q] = s;
        s = S1[q];
        s.x = fmaf(a.x, s.x, bm.x * x1); s.y = fmaf(a.y, s.y, bm.y * x1);
        s.z = fmaf(a.z, s.z, bm.z * x1); s.w = fmaf(a.w, s.w, bm.w * x1);
        acc1 += c.x * s.x + c.y * s.y + c.z * s.z + c.w * s.w;
        S1[q] = s;
    }
    float dd = D0[t];
    g_gact[b0 * HSZ + t] = gelu_exact(fmaf(dd, x0, acc0));
    g_gact[(b0 + 1) * HSZ + t] = gelu_exact(fmaf(dd, x1, acc1));
}

// ============================================================
// Launch: 3 setup + 63 x 4 = 255 graph nodes
// ============================================================
extern "C" void kernel_launch(void* const* d_in, const int* in_sizes, int n_in,
                              void* d_out, int out_size) {
    int o = (n_in >= 14) ? 1 : 0;   // skip scalar autoregressive_steps if present
    const float* inseq = (const float*)d_in[0];
    const float* inW = (const float*)d_in[1 + o];
    const float* inb = (const float*)d_in[2 + o];
    const float* A   = (const float*)d_in[3 + o];
    const float* Bm  = (const float*)d_in[4 + o];
    const float* Cm  = (const float*)d_in[5 + o];
    const float* D   = (const float*)d_in[6 + o];
    const float* oW  = (const float*)d_in[7 + o];
    const float* ob  = (const float*)d_in[8 + o];
    const float* lng = (const float*)d_in[9 + o];
    const float* lnb = (const float*)d_in[10 + o];
    const float* hW  = (const float*)d_in[11 + o];
    const float* hb  = (const float*)d_in[12 + o];
    float* out = (float*)d_out;

    const float *A1 = A + HSZ * NSZ, *B1 = Bm + HSZ * NSZ, *C1 = Cm + HSZ * NSZ, *D1 = D + HSZ;
    const float *oW1 = oW + HSZ * HSZ, *ob1 = ob + HSZ;
    const float *lng1 = lng + HSZ, *lnb1 = lnb + HSZ;

    k_enc<<<(BSZ * 6 * HSZ) / 256, 256>>>(inseq, inW, inb);
    k_init<<<(2 * BSZ * HSZ * NSZ) / 256, 256>>>();
    k_first<<<(BSZ * HSZ) / 256, 256>>>(inW, inb, A, Bm, Cm, D);

    dim3 gg(4, 4, KC);   // 4 colblocks x 4 rowblocks x 16 K-chunks = 256 blocks
    for (int i = 0; i < TSTEPS; i++) {
        int s0 = (i == 0) ? 1 : 0;
        k_gemm<<<gg, 256>>>(oW);                                     // layer 0 GEMM
        k_ssm1<<<BSZ / 2, 512>>>(s0, ob, lng, lnb, A1, B1, C1, D1);  // +LN0, layer-1 SSM
        k_gemm<<<gg, 256>>>(oW1);                                    // layer 1 GEMM
        k_head<<<BSZ / 2, 512>>>(i, ob1, lng1, lnb1, hW, hb,
                                 inW, inb, A, Bm, Cm, D, out);       // +LN1, head, next ssm0
    }
}

// round 6
// speedup vs baseline: 1.0818x; 1.0818x over previous
#include <cuda_runtime.h>

#define BSZ 256
#define HSZ 512
#define NSZ 16
#define TSTEPS 63
#define ODIM 9
#define KC 8            // split-K chunks
#define KCH 64          // K per chunk

typedef unsigned long long ull;

// ---------- packed f32x2 helpers (sm_103a FFMA2 path, PTX-only) ----------
__device__ __forceinline__ ull pack2(float lo, float hi) {
    ull r; asm("mov.b64 %0,{%1,%2};" : "=l"(r) : "f"(lo), "f"(hi)); return r;
}
__device__ __forceinline__ float2 unpack2(ull v) {
    float2 r; asm("mov.b64 {%0,%1},%2;" : "=f"(r.x), "=f"(r.y) : "l"(v)); return r;
}
__device__ __forceinline__ ull fma2v(ull a, ull b, ull c) {
    ull d; asm("fma.rn.f32x2 %0,%1,%2,%3;" : "=l"(d) : "l"(a), "l"(b), "l"(c)); return d;
}

__device__ __forceinline__ float gelu_exact(float x) {
    return 0.5f * x * (1.0f + erff(x * 0.70710678118654752440f));
}
__device__ __forceinline__ float sigm(float x) {
    return 1.0f / (1.0f + expf(-x));
}

// ---------- scratch (__device__ globals; no allocation allowed) ----------
__device__ __align__(16) float g_enc[BSZ * 6 * HSZ];          // encoded[:, 0:6, :] only
__device__ __align__(16) float g_states[2 * BSZ * HSZ * NSZ]; // SSM states per layer
__device__ __align__(16) float g_gact[BSZ * HSZ];             // gelu(y) GEMM input
__device__ __align__(16) float g_dp[BSZ * HSZ];               // decoder proj (step 0)
__device__ __align__(16) float g_ctx[BSZ * HSZ];
__device__ __align__(16) float g_part[KC * BSZ * HSZ];        // split-K GEMM partials

// ============================================================
// encoded = input_seq @ in_W + in_b  (only s < 6 ever read: ptr in [0,6))
// ============================================================
__global__ void k_enc(const float* __restrict__ inseq,
                      const float* __restrict__ inW,
                      const float* __restrict__ inb) {
    int idx = blockIdx.x * 256 + threadIdx.x;   // < B*6*H
    int h = idx & (HSZ - 1);
    int bs = idx >> 9;                          // b*6 + s
    int b = bs / 6, s = bs - b * 6;
    const float* r = inseq + (b * 64 + s) * 3;
    g_enc[idx] = fmaf(r[0], inW[h],
                 fmaf(r[1], inW[HSZ + h],
                 fmaf(r[2], inW[2 * HSZ + h], inb[h])));
}

// ============================================================
// zero states / ctx
// ============================================================
__global__ void k_init() {
    int idx = blockIdx.x * 256 + threadIdx.x;
    if (idx < 2 * BSZ * HSZ * NSZ) g_states[idx] = 0.0f;
    if (idx < BSZ * HSZ) g_ctx[idx] = 0.0f;
}

// ============================================================
// Step-0 decoder proj + layer-0 SSM (dec0 = [0,0,1], states = 0)
// ============================================================
__global__ void __launch_bounds__(256)
k_first(const float* __restrict__ inW, const float* __restrict__ inb,
        const float* __restrict__ A0, const float* __restrict__ B0,
        const float* __restrict__ C0, const float* __restrict__ D0) {
    int idx = blockIdx.x * 256 + threadIdx.x;   // < B*H
    int h = idx & (HSZ - 1);
    int b = idx >> 9;
    float x = inW[2 * HSZ + h] + inb[h];
    g_dp[idx] = x;

    const float4* B4 = (const float4*)(B0 + h * NSZ);
    const float4* C4 = (const float4*)(C0 + h * NSZ);
    float4* S4p = (float4*)(g_states + ((size_t)b * HSZ + h) * NSZ);
    float acc = 0.0f;
#pragma unroll
    for (int q = 0; q < 4; q++) {
        float4 bm = B4[q], c = C4[q];
        float4 s = make_float4(bm.x * x, bm.y * x, bm.z * x, bm.w * x);
        acc += c.x * s.x + c.y * s.y + c.z * s.z + c.w * s.w;
        S4p[q] = s;
    }
    g_gact[idx] = gelu_exact(fmaf(D0[h], x, acc));
}

// ============================================================
// Split-K GEMM: g_part[z] = g_gact(256x512) @ W k-chunk z
// grid (4 ncb, 16 mrb, 8 kc) = 512 blocks, 64 threads.
// Block tile 16x128, chunk 64. Per-thread: 8 rows (4 row-pairs) x 4 cols,
// row-pair f32x2 (same inner loop as the 2094us R4 kernel; only BM halved
// and thread count halved so per-thread work is identical).
// ============================================================
__global__ void __launch_bounds__(64)
k_gemm(const float* __restrict__ W) {
    __shared__ float As[KCH][18];     // transposed: As[k][r], r<16, pad 18 (8B align)
    __shared__ float Bs[KCH][128];
    int t = threadIdx.x, lane = t & 31, w = t >> 5;
    int n0 = blockIdx.x * 128, m0 = blockIdx.y * 16, k0 = blockIdx.z * KCH;

    // stage A: 16 rows x 64 k, transposed (4 float4 loads/thread)
    {
        int kk = (t & 15) * 4, rr = t >> 4;     // rr 0..3
#pragma unroll
        for (int p = 0; p < 4; p++) {
            int r = rr + 4 * p;
            float4 v = *(const float4*)&g_gact[(m0 + r) * HSZ + k0 + kk];
            As[kk + 0][r] = v.x;
            As[kk + 1][r] = v.y;
            As[kk + 2][r] = v.z;
            As[kk + 3][r] = v.w;
        }
    }
    // stage B: 64 k x 128 cols (32 float4 loads/thread)
    {
        int cc = (t & 31) * 4, kk = t >> 5;     // kk 0..1
#pragma unroll
        for (int p = 0; p < 32; p++)
            *(float4*)&Bs[kk + 2 * p][cc] = *(const float4*)&W[(k0 + kk + 2 * p) * HSZ + n0 + cc];
    }
    __syncthreads();

    ull acc[4][4];
#pragma unroll
    for (int i = 0; i < 4; i++)
#pragma unroll
        for (int j = 0; j < 4; j++) acc[i][j] = 0ULL;

    int rbase = w * 8;        // warp rows [m0+8w, m0+8w+8)
    int cbase = lane * 4;     // lane cols [n0+4l, n0+4l+4)

#pragma unroll 8
    for (int k = 0; k < KCH; k++) {
        float4 bv = *(const float4*)&Bs[k][cbase];
        ull b0 = pack2(bv.x, bv.x), b1 = pack2(bv.y, bv.y);
        ull b2 = pack2(bv.z, bv.z), b3 = pack2(bv.w, bv.w);
#pragma unroll
        for (int rp = 0; rp < 4; rp++) {
            ull av = *(const ull*)&As[k][rbase + rp * 2];   // broadcast (r, r+1)
            acc[rp][0] = fma2v(av, b0, acc[rp][0]);
            acc[rp][1] = fma2v(av, b1, acc[rp][1]);
            acc[rp][2] = fma2v(av, b2, acc[rp][2]);
            acc[rp][3] = fma2v(av, b3, acc[rp][3]);
        }
    }

    float* P = g_part + (size_t)blockIdx.z * BSZ * HSZ;
#pragma unroll
    for (int rp = 0; rp < 4; rp++) {
        int row = m0 + rbase + rp * 2;
#pragma unroll
        for (int c = 0; c < 4; c++) {
            float2 v = unpack2(acc[rp][c]);
            int col = n0 + cbase + c;
            P[row * HSZ + col] = v.x;
            P[(row + 1) * HSZ + col] = v.y;
        }
    }
}

// ---------- deterministic block LN over 512 threads ----------
__device__ __forceinline__ void blk_ln(float z, int t, int lane, int w,
                                       float* red, float& m, float& rstd) {
    float s = z, q = z * z;
#pragma unroll
    for (int d = 16; d; d >>= 1) {
        s += __shfl_xor_sync(0xFFFFFFFFu, s, d);
        q += __shfl_xor_sync(0xFFFFFFFFu, q, d);
    }
    if (lane == 0) { red[w] = s; red[16 + w] = q; }
    __syncthreads();
    if (t == 0) {
        float ss = 0.0f, qq = 0.0f;
#pragma unroll
        for (int i = 0; i < 16; i++) { ss += red[i]; qq += red[16 + i]; }
        float mm = ss * (1.0f / HSZ);
        red[32] = mm;
        red[33] = rsqrtf(qq * (1.0f / HSZ) - mm * mm + 1e-5f);
    }
    __syncthreads();
    m = red[32]; rstd = red[33];
}

// ============================================================
// ssm1: z0 = sum(partials)+bias (+residual), LN -> x, layer-1 SSM -> g_gact
// block per batch row, 512 threads (t = h)
// ============================================================
__global__ void __launch_bounds__(512)
k_ssm1(int isstep0,
       const float* __restrict__ ob0, const float* __restrict__ lng0,
       const float* __restrict__ lnb0,
       const float* __restrict__ A1, const float* __restrict__ B1,
       const float* __restrict__ C1, const float* __restrict__ D1) {
    __shared__ float red[34];
    int b = blockIdx.x, t = threadIdx.x;
    int lane = t & 31, w = t >> 5;

    float y = 0.0f;
#pragma unroll
    for (int z = 0; z < KC; z++) y += g_part[((size_t)z * BSZ + b) * HSZ + t];
    y += ob0[t];
    float zz = isstep0 ? (y + g_dp[b * HSZ + t]) : (2.0f * y);

    float m, rstd;
    blk_ln(zz, t, lane, w, red, m, rstd);
    float x = (zz - m) * rstd * lng0[t] + lnb0[t];

    const float4* A4 = (const float4*)(A1 + t * NSZ);
    const float4* B4 = (const float4*)(B1 + t * NSZ);
    const float4* C4 = (const float4*)(C1 + t * NSZ);
    float4* S4p = (float4*)(g_states + ((size_t)BSZ * HSZ + (size_t)b * HSZ + t) * NSZ);
    float acc = 0.0f;
#pragma unroll
    for (int q = 0; q < 4; q++) {
        float4 a = A4[q], bm = B4[q], c = C4[q], s = S4p[q];
        s.x = fmaf(a.x, s.x, bm.x * x);
        s.y = fmaf(a.y, s.y, bm.y * x);
        s.z = fmaf(a.z, s.z, bm.z * x);
        s.w = fmaf(a.w, s.w, bm.w * x);
        acc += c.x * s.x + c.y * s.y + c.z * s.z + c.w * s.w;
        S4p[q] = s;
    }
    g_gact[b * HSZ + t] = gelu_exact(fmaf(D1[t], x, acc));
}

// ============================================================
// head (+ fused next-step decoder proj & layer-0 SSM)
// block per batch row, 512 threads
// ============================================================
__global__ void __launch_bounds__(512)
k_head(int step,
       const float* __restrict__ ob1, const float* __restrict__ lng1,
       const float* __restrict__ lnb1,
       const float* __restrict__ hW, const float* __restrict__ hb,
       const float* __restrict__ inW, const float* __restrict__ inb,
       const float* __restrict__ A0, const float* __restrict__ B0,
       const float* __restrict__ C0, const float* __restrict__ D0,
       float* __restrict__ out) {
    __shared__ float xdc[HSZ];
    __shared__ float red[34];
    __shared__ float gv[12];
    __shared__ float decs[3];
    __shared__ int ptr_s;

    int b = blockIdx.x, t = threadIdx.x;
    int lane = t & 31, w = t >> 5;

    // z1 from split-K partials
    float y = 0.0f;
#pragma unroll
    for (int z = 0; z < KC; z++) y += g_part[((size_t)z * BSZ + b) * HSZ + t];
    y += ob1[t];
    float zz = (step == 0) ? (y + g_dp[b * HSZ + t]) : (2.0f * y);

    float m, rstd;
    blk_ln(zz, t, lane, w, red, m, rstd);
    float xd = (zz - m) * rstd * lng1[t] + lnb1[t];
    float ctxv = g_ctx[b * HSZ + t];
    xdc[t] = xd + ctxv;
    __syncthreads();

    // head logits: warp w (<9) computes dot(xdc, head_W[:,w]) + head_b[w]
    if (w < ODIM) {
        float a = 0.0f;
#pragma unroll
        for (int q = 0; q < 16; q++) {
            int k = q * 32 + lane;
            a = fmaf(xdc[k], hW[k * ODIM + w], a);
        }
#pragma unroll
        for (int d = 16; d; d >>= 1) a += __shfl_xor_sync(0xFFFFFFFFu, a, d);
        if (lane == 0) gv[w] = a + hb[w];
    }
    __syncthreads();

    bool is_out = ((step & 1) == 0);
    if (is_out) {
        if (t < ODIM) out[b * (TSTEPS * ODIM) + step * ODIM + t] = sigm(gv[t]);
        if (t == 0) {
            decs[0] = (sigm(gv[0]) > 0.5f) ? 1.0f : 0.0f;
            decs[1] = 1.0f; decs[2] = 0.0f;
        }
    } else {
        if (t == 0) {
            float best = sigm(gv[3]); int p = 0;
#pragma unroll
            for (int c = 1; c < 6; c++) {
                float v = sigm(gv[3 + c]);
                if (v > best) { best = v; p = c; }
            }
            ptr_s = p;
            decs[0] = 0.0f; decs[1] = 0.0f; decs[2] = 1.0f;
        }
        __syncthreads();                       // uniform branch: safe
        const float* ev = g_enc + (b * 6 + ptr_s) * HSZ;
        g_ctx[b * HSZ + t] = ctxv + ev[t];     // ctx += ptr_vec
        if (w < ODIM) {
            float a2 = 0.0f;
#pragma unroll
            for (int q = 0; q < 16; q++) {
                int k = q * 32 + lane;
                a2 = fmaf(ev[k], hW[k * ODIM + w], a2);
            }
#pragma unroll
            for (int d = 16; d; d >>= 1) a2 += __shfl_xor_sync(0xFFFFFFFFu, a2, d);
            if (lane == 0)
                out[b * (TSTEPS * ODIM) + step * ODIM + w] = sigm(gv[w] + a2);
        }
    }
    __syncthreads();

    // fused next-step: decoder proj + layer-0 SSM (harmless on last step)
    float d0 = decs[0], d1 = decs[1], d2 = decs[2];
    float x = fmaf(d0, inW[t], fmaf(d1, inW[HSZ + t], fmaf(d2, inW[2 * HSZ + t], inb[t])));

    const float4* A4 = (const float4*)(A0 + t * NSZ);
    const float4* B4 = (const float4*)(B0 + t * NSZ);
    const float4* C4 = (const float4*)(C0 + t * NSZ);
    float4* S4p = (float4*)(g_states + ((size_t)b * HSZ + t) * NSZ);
    float acc = 0.0f;
#pragma unroll
    for (int q = 0; q < 4; q++) {
        float4 a = A4[q], bm = B4[q], c = C4[q], s = S4p[q];
        s.x = fmaf(a.x, s.x, bm.x * x);
        s.y = fmaf(a.y, s.y, bm.y * x);
        s.z = fmaf(a.z, s.z, bm.z * x);
        s.w = fmaf(a.w, s.w, bm.w * x);
        acc += c.x * s.x + c.y * s.y + c.z * s.z + c.w * s.w;
        S4p[q] = s;
    }
    g_gact[b * HSZ + t] = gelu_exact(fmaf(D0[t], x, acc));
}

// ============================================================
// Launch: 3 setup + 63 x 4 = 255 graph nodes
// ============================================================
extern "C" void kernel_launch(void* const* d_in, const int* in_sizes, int n_in,
                              void* d_out, int out_size) {
    int o = (n_in >= 14) ? 1 : 0;   // skip scalar autoregressive_steps if present
    const float* inseq = (const float*)d_in[0];
    const float* inW = (const float*)d_in[1 + o];
    const float* inb = (const float*)d_in[2 + o];
    const float* A   = (const float*)d_in[3 + o];
    const float* Bm  = (const float*)d_in[4 + o];
    const float* Cm  = (const float*)d_in[5 + o];
    const float* D   = (const float*)d_in[6 + o];
    const float* oW  = (const float*)d_in[7 + o];
    const float* ob  = (const float*)d_in[8 + o];
    const float* lng = (const float*)d_in[9 + o];
    const float* lnb = (const float*)d_in[10 + o];
    const float* hW  = (const float*)d_in[11 + o];
    const float* hb  = (const float*)d_in[12 + o];
    float* out = (float*)d_out;

    const float *A1 = A + HSZ * NSZ, *B1 = Bm + HSZ * NSZ, *C1 = Cm + HSZ * NSZ, *D1 = D + HSZ;
    const float *oW1 = oW + HSZ * HSZ, *ob1 = ob + HSZ;
    const float *lng1 = lng + HSZ, *lnb1 = lnb + HSZ;

    k_enc<<<(BSZ * 6 * HSZ) / 256, 256>>>(inseq, inW, inb);
    k_init<<<(2 * BSZ * HSZ * NSZ) / 256, 256>>>();
    k_first<<<(BSZ * HSZ) / 256, 256>>>(inW, inb, A, Bm, Cm, D);

    dim3 gg(4, 16, KC);   // 4 colblocks x 16 rowblocks x 8 K-chunks = 512 blocks
    for (int i = 0; i < TSTEPS; i++) {
        int s0 = (i == 0) ? 1 : 0;
        k_gemm<<<gg, 64>>>(oW);                                     // layer 0 GEMM
        k_ssm1<<<BSZ, 512>>>(s0, ob, lng, lnb, A1, B1, C1, D1);     // +LN0, layer-1 SSM
        k_gemm<<<gg, 64>>>(oW1);                                    // layer 1 GEMM
        k_head<<<BSZ, 512>>>(i, ob1, lng1, lnb1, hW, hb,
                             inW, inb, A, Bm, Cm, D, out);          // +LN1, head, next ssm0
    }
}